// round 16
// baseline (speedup 1.0000x reference)
#include <cuda_runtime.h>
#include <cstdint>

// Problem constants (fixed by the reference)
#define BB 32
#define QQ 900
#define CC 92
#define BIGV 100000000.0f
#define TI 25          // i-rows per block -> grid.x = 36, 1152 blocks
#define NPST 28        // padded ii-stride of transposed prob table

__device__ __forceinline__ float fast_rcp(float x) {
    float r;
    asm("rcp.approx.ftz.f32 %0, %1;" : "=f"(r) : "f"(x));
    return r;
}

// ---------------------------------------------------------------------------
// Fused kernel: per-block softmax into a TRANSPOSED (1-p) table, then the
// cost body in midpoint form:
//   overlap_unclamped = (hp + hg) - max(|dc|, |dh|)
//   enclose           = (hp + hg) + max(|dc|, |dh|)
//   cost = 0.25u + 0.5v + (1 - prob) - inter/uni - uni/enc
// Warps 0-6 (224 thr x 4 j) cover j=0..895; warp 7 covers the j=896..899
// strip. 5 blocks/SM target (regs <= 52) to raise issue occupancy.
// ---------------------------------------------------------------------------
__global__ __launch_bounds__(256, 5)
void cost_kernel(const float* __restrict__ pred_logits,
                 const float* __restrict__ pred_boxes,
                 const float* __restrict__ boxes,
                 const float* __restrict__ area,
                 const int*   __restrict__ labels,
                 float* __restrict__ out) {
    const int b  = blockIdx.y;
    const int i0 = blockIdx.x * TI;
    const int tid = threadIdx.x;
    const int wid = tid >> 5;
    const int lane = tid & 31;

    __shared__ float  s_npT[CC][NPST];  // (1 - prob), transposed: [class][ii]
    __shared__ float4 s_cb[TI];         // pred box (cx, cy, w/2, h/2)
    __shared__ float  s_a1[TI];         // pred box area w*h

    // ---- fused softmax (warp-per-row), write transposed ----
    for (int row = wid; row < TI; row += 8) {
        const float* in = pred_logits + ((size_t)(b * QQ + i0 + row)) * CC;
        float v0 = in[lane];
        float v1 = in[lane + 32];
        bool has2 = lane < (CC - 64);          // lane < 28
        float v2 = has2 ? in[lane + 64] : -1e30f;

        float m = fmaxf(fmaxf(v0, v1), v2);
        #pragma unroll
        for (int o = 16; o > 0; o >>= 1)
            m = fmaxf(m, __shfl_xor_sync(0xFFFFFFFFu, m, o));

        float e0 = __expf(v0 - m);
        float e1 = __expf(v1 - m);
        float e2 = has2 ? __expf(v2 - m) : 0.0f;
        float s = e0 + e1 + e2;
        #pragma unroll
        for (int o = 16; o > 0; o >>= 1)
            s += __shfl_xor_sync(0xFFFFFFFFu, s, o);

        float inv = __fdividef(1.0f, s);
        s_npT[lane][row]      = fmaf(e0, -inv, 1.0f);
        s_npT[lane + 32][row] = fmaf(e1, -inv, 1.0f);
        if (has2) s_npT[lane + 64][row] = fmaf(e2, -inv, 1.0f);
    }
    // ---- per-i box precomputes ----
    if (tid < TI) {
        float4 pb = reinterpret_cast<const float4*>(pred_boxes)[b * QQ + i0 + tid];
        s_cb[tid] = make_float4(pb.x, pb.y, 0.5f * pb.z, 0.5f * pb.w);
        s_a1[tid] = pb.z * pb.w;
    }
    __syncthreads();

    if (tid < 224) {
        // ==== main path: 224 threads, 4 consecutive j each (j = 0..895) ====
        const int j0 = tid * 4;

        float gcx[4], gcy[4], hgz[4], hgw[4], a2[4];
        bool  valid[4];
        const float* npp[4];                // &s_npT[lab[t]][0]
        #pragma unroll
        for (int t = 0; t < 4; t++) {
            float4 g = reinterpret_cast<const float4*>(boxes)[b * QQ + j0 + t];
            gcx[t] = g.x; gcy[t] = g.y;
            hgz[t] = 0.5f * g.z; hgw[t] = 0.5f * g.w;
            a2[t]  = g.z * g.w;
            npp[t] = &s_npT[labels[b * QQ + j0 + t]][0];
            valid[t] = area[b * QQ + j0 + t] > 0.0f;
        }

        float* obase = out + ((size_t)(b * QQ + i0)) * QQ + j0;

        #pragma unroll 3
        for (int g = 0; g < 12; g++) {
            float2 np2[4];
            #pragma unroll
            for (int t = 0; t < 4; t++)
                np2[t] = *reinterpret_cast<const float2*>(npp[t] + 2 * g);

            #pragma unroll
            for (int k = 0; k < 2; k++) {
                const int ii = 2 * g + k;
                float4 pc = s_cb[ii];
                float  a1 = s_a1[ii];
                float4 res;
                float* r = &res.x;
                #pragma unroll
                for (int t = 0; t < 4; t++) {
                    float np = k ? np2[t].y : np2[t].x;
                    float d0 = pc.x - gcx[t], d1 = pc.y - gcy[t];
                    float d2 = pc.z - hgz[t], d3 = pc.w - hgw[t];
                    float u = fabsf(d0) + fabsf(d1);
                    float v = fabsf(d2) + fabsf(d3);
                    float mx = fmaxf(fabsf(d0), fabsf(d2));
                    float my = fmaxf(fabsf(d1), fabsf(d3));
                    float sz = pc.z + hgz[t], sw = pc.w + hgw[t];
                    float iwu = sz - mx, ihu = sw - my;
                    float ew  = sz + mx, eh  = sw + my;
                    float iw = fmaxf(iwu, 0.0f), ih = fmaxf(ihu, 0.0f);
                    float inter = iw * ih;
                    float enc   = ew * eh;
                    float uni   = (a1 + a2[t]) - inter;
                    float ru = fast_rcp(uni);
                    float re = fast_rcp(enc);
                    float base = fmaf(v, 0.5f, np);
                    base = fmaf(u, 0.25f, base);
                    base = fmaf(-uni, re, base);
                    float cost = fmaf(-inter, ru, base);
                    r[t] = valid[t] ? cost : BIGV;
                }
                reinterpret_cast<float4*>(obase + (size_t)ii * QQ)[0] = res;
            }
        }
        { // remainder ii = 24
            const int ii = 24;
            float4 pc = s_cb[ii];
            float  a1 = s_a1[ii];
            float4 res;
            float* r = &res.x;
            #pragma unroll
            for (int t = 0; t < 4; t++) {
                float np = npp[t][ii];
                float d0 = pc.x - gcx[t], d1 = pc.y - gcy[t];
                float d2 = pc.z - hgz[t], d3 = pc.w - hgw[t];
                float u = fabsf(d0) + fabsf(d1);
                float v = fabsf(d2) + fabsf(d3);
                float mx = fmaxf(fabsf(d0), fabsf(d2));
                float my = fmaxf(fabsf(d1), fabsf(d3));
                float sz = pc.z + hgz[t], sw = pc.w + hgw[t];
                float iwu = sz - mx, ihu = sw - my;
                float ew  = sz + mx, eh  = sw + my;
                float iw = fmaxf(iwu, 0.0f), ih = fmaxf(ihu, 0.0f);
                float inter = iw * ih;
                float enc   = ew * eh;
                float uni   = (a1 + a2[t]) - inter;
                float ru = fast_rcp(uni);
                float re = fast_rcp(enc);
                float base = fmaf(v, 0.5f, np);
                base = fmaf(u, 0.25f, base);
                base = fmaf(-uni, re, base);
                float cost = fmaf(-inter, ru, base);
                r[t] = valid[t] ? cost : BIGV;
            }
            reinterpret_cast<float4*>(obase + (size_t)ii * QQ)[0] = res;
        }
    } else if (lane < TI) {
        // ==== warp 7: strip j = 896..899, one i-row (ii = lane) per lane ====
        const int ii = lane;
        const int j0 = 896;
        float4 pc = s_cb[ii];
        float  a1 = s_a1[ii];
        float4 res;
        float* r = &res.x;
        #pragma unroll
        for (int t = 0; t < 4; t++) {
            float4 g = reinterpret_cast<const float4*>(boxes)[b * QQ + j0 + t];
            float np = s_npT[labels[b * QQ + j0 + t]][ii];
            bool  vd = area[b * QQ + j0 + t] > 0.0f;
            float hgz = 0.5f * g.z, hgw = 0.5f * g.w;
            float a2 = g.z * g.w;
            float d0 = pc.x - g.x, d1 = pc.y - g.y;
            float d2 = pc.z - hgz, d3 = pc.w - hgw;
            float u = fabsf(d0) + fabsf(d1);
            float v = fabsf(d2) + fabsf(d3);
            float mx = fmaxf(fabsf(d0), fabsf(d2));
            float my = fmaxf(fabsf(d1), fabsf(d3));
            float sz = pc.z + hgz, sw = pc.w + hgw;
            float iwu = sz - mx, ihu = sw - my;
            float ew  = sz + mx, eh  = sw + my;
            float iw = fmaxf(iwu, 0.0f), ih = fmaxf(ihu, 0.0f);
            float inter = iw * ih;
            float enc   = ew * eh;
            float uni   = (a1 + a2) - inter;
            float ru = fast_rcp(uni);
            float re = fast_rcp(enc);
            float base = fmaf(v, 0.5f, np);
            base = fmaf(u, 0.25f, base);
            base = fmaf(-uni, re, base);
            float cost = fmaf(-inter, ru, base);
            r[t] = vd ? cost : BIGV;
        }
        float* op = out + ((size_t)(b * QQ + i0 + ii)) * QQ + j0;
        reinterpret_cast<float4*>(op)[0] = res;
    }
}

extern "C" void kernel_launch(void* const* d_in, const int* in_sizes, int n_in,
                              void* d_out, int out_size) {
    const float* pred_logits = (const float*)d_in[0];  // [B,Q,C]
    const float* pred_boxes  = (const float*)d_in[1];  // [B,Q,4]
    const float* boxes       = (const float*)d_in[2];  // [B,Q,4]
    const float* area        = (const float*)d_in[3];  // [B,Q]
    const int*   labels      = (const int*)d_in[4];    // [B,Q]
    float* out = (float*)d_out;                        // [B,Q,Q]

    dim3 grid(QQ / TI, BB);             // (36, 32) = 1152 blocks
    cost_kernel<<<grid, 256>>>(pred_logits, pred_boxes, boxes, area, labels, out);
}

// round 17
// speedup vs baseline: 1.1053x; 1.1053x over previous
#include <cuda_runtime.h>
#include <cstdint>

// Problem constants (fixed by the reference)
#define BB 32
#define QQ 900
#define CC 92
#define BIGV 100000000.0f
#define TI 25          // i-rows per block -> grid.x = 36, 1152 blocks
#define NPST 30        // padded ii-stride: (15c+g) mod 16 uniform -> low LDS.64 conflicts

__device__ __forceinline__ float fast_rcp(float x) {
    float r;
    asm("rcp.approx.ftz.f32 %0, %1;" : "=f"(r) : "f"(x));
    return r;
}

// ---------------------------------------------------------------------------
// Fused kernel: per-block softmax into a TRANSPOSED (1-p) table, then the
// cost body in midpoint form:
//   overlap_unclamped = (hp + hg) - max(|dc|, |dh|)
//   enclose           = (hp + hg) + max(|dc|, |dh|)
//   cost = 0.25u + 0.5v + (1 - prob) - inter/uni - uni/enc
// Warps 0-6 (224 thr x 4 j) cover j=0..895; warp 7 covers the j=896..899 strip.
// ---------------------------------------------------------------------------
__global__ __launch_bounds__(256, 4)
void cost_kernel(const float* __restrict__ pred_logits,
                 const float* __restrict__ pred_boxes,
                 const float* __restrict__ boxes,
                 const float* __restrict__ area,
                 const int*   __restrict__ labels,
                 float* __restrict__ out) {
    const int b  = blockIdx.y;
    const int i0 = blockIdx.x * TI;
    const int tid = threadIdx.x;
    const int wid = tid >> 5;
    const int lane = tid & 31;

    __shared__ float  s_npT[CC][NPST];  // (1 - prob), transposed: [class][ii]
    __shared__ float4 s_cb[TI];         // pred box (cx, cy, w/2, h/2)
    __shared__ float  s_a1[TI];         // pred box area w*h

    // ---- fused softmax (warp-per-row), write transposed ----
    for (int row = wid; row < TI; row += 8) {
        const float* in = pred_logits + ((size_t)(b * QQ + i0 + row)) * CC;
        float v0 = in[lane];
        float v1 = in[lane + 32];
        bool has2 = lane < (CC - 64);          // lane < 28
        float v2 = has2 ? in[lane + 64] : -1e30f;

        float m = fmaxf(fmaxf(v0, v1), v2);
        #pragma unroll
        for (int o = 16; o > 0; o >>= 1)
            m = fmaxf(m, __shfl_xor_sync(0xFFFFFFFFu, m, o));

        float e0 = __expf(v0 - m);
        float e1 = __expf(v1 - m);
        float e2 = has2 ? __expf(v2 - m) : 0.0f;
        float s = e0 + e1 + e2;
        #pragma unroll
        for (int o = 16; o > 0; o >>= 1)
            s += __shfl_xor_sync(0xFFFFFFFFu, s, o);

        float inv = __fdividef(1.0f, s);
        s_npT[lane][row]      = fmaf(e0, -inv, 1.0f);
        s_npT[lane + 32][row] = fmaf(e1, -inv, 1.0f);
        if (has2) s_npT[lane + 64][row] = fmaf(e2, -inv, 1.0f);
    }
    // ---- per-i box precomputes ----
    if (tid < TI) {
        float4 pb = reinterpret_cast<const float4*>(pred_boxes)[b * QQ + i0 + tid];
        s_cb[tid] = make_float4(pb.x, pb.y, 0.5f * pb.z, 0.5f * pb.w);
        s_a1[tid] = pb.z * pb.w;
    }
    __syncthreads();

    if (tid < 224) {
        // ==== main path: 224 threads, 4 consecutive j each (j = 0..895) ====
        const int j0 = tid * 4;

        float gcx[4], gcy[4], hgz[4], hgw[4], a2[4];
        bool  valid[4];
        const float* npp[4];                // &s_npT[lab[t]][0]
        #pragma unroll
        for (int t = 0; t < 4; t++) {
            float4 g = reinterpret_cast<const float4*>(boxes)[b * QQ + j0 + t];
            gcx[t] = g.x; gcy[t] = g.y;
            hgz[t] = 0.5f * g.z; hgw[t] = 0.5f * g.w;
            a2[t]  = g.z * g.w;
            npp[t] = &s_npT[labels[b * QQ + j0 + t]][0];
            valid[t] = area[b * QQ + j0 + t] > 0.0f;
        }

        float* obase = out + ((size_t)(b * QQ + i0)) * QQ + j0;

        #pragma unroll 3
        for (int g = 0; g < 12; g++) {
            float2 np2[4];
            #pragma unroll
            for (int t = 0; t < 4; t++)
                np2[t] = *reinterpret_cast<const float2*>(npp[t] + 2 * g);

            #pragma unroll
            for (int k = 0; k < 2; k++) {
                const int ii = 2 * g + k;
                float4 pc = s_cb[ii];
                float  a1 = s_a1[ii];
                float4 res;
                float* r = &res.x;
                #pragma unroll
                for (int t = 0; t < 4; t++) {
                    float np = k ? np2[t].y : np2[t].x;
                    float d0 = pc.x - gcx[t], d1 = pc.y - gcy[t];
                    float d2 = pc.z - hgz[t], d3 = pc.w - hgw[t];
                    float u = fabsf(d0) + fabsf(d1);
                    float v = fabsf(d2) + fabsf(d3);
                    float mx = fmaxf(fabsf(d0), fabsf(d2));
                    float my = fmaxf(fabsf(d1), fabsf(d3));
                    float sz = pc.z + hgz[t], sw = pc.w + hgw[t];
                    float iwu = sz - mx, ihu = sw - my;
                    float ew  = sz + mx, eh  = sw + my;
                    float iw = fmaxf(iwu, 0.0f), ih = fmaxf(ihu, 0.0f);
                    float inter = iw * ih;
                    float enc   = ew * eh;
                    float uni   = (a1 + a2[t]) - inter;
                    float ru = fast_rcp(uni);
                    float re = fast_rcp(enc);
                    float base = fmaf(v, 0.5f, np);
                    base = fmaf(u, 0.25f, base);
                    base = fmaf(-uni, re, base);
                    float cost = fmaf(-inter, ru, base);
                    r[t] = valid[t] ? cost : BIGV;
                }
                reinterpret_cast<float4*>(obase + (size_t)ii * QQ)[0] = res;
            }
        }
        { // remainder ii = 24
            const int ii = 24;
            float4 pc = s_cb[ii];
            float  a1 = s_a1[ii];
            float4 res;
            float* r = &res.x;
            #pragma unroll
            for (int t = 0; t < 4; t++) {
                float np = npp[t][ii];
                float d0 = pc.x - gcx[t], d1 = pc.y - gcy[t];
                float d2 = pc.z - hgz[t], d3 = pc.w - hgw[t];
                float u = fabsf(d0) + fabsf(d1);
                float v = fabsf(d2) + fabsf(d3);
                float mx = fmaxf(fabsf(d0), fabsf(d2));
                float my = fmaxf(fabsf(d1), fabsf(d3));
                float sz = pc.z + hgz[t], sw = pc.w + hgw[t];
                float iwu = sz - mx, ihu = sw - my;
                float ew  = sz + mx, eh  = sw + my;
                float iw = fmaxf(iwu, 0.0f), ih = fmaxf(ihu, 0.0f);
                float inter = iw * ih;
                float enc   = ew * eh;
                float uni   = (a1 + a2[t]) - inter;
                float ru = fast_rcp(uni);
                float re = fast_rcp(enc);
                float base = fmaf(v, 0.5f, np);
                base = fmaf(u, 0.25f, base);
                base = fmaf(-uni, re, base);
                float cost = fmaf(-inter, ru, base);
                r[t] = valid[t] ? cost : BIGV;
            }
            reinterpret_cast<float4*>(obase + (size_t)ii * QQ)[0] = res;
        }
    } else if (lane < TI) {
        // ==== warp 7: strip j = 896..899, one i-row (ii = lane) per lane ====
        const int ii = lane;
        const int j0 = 896;
        float4 pc = s_cb[ii];
        float  a1 = s_a1[ii];
        float4 res;
        float* r = &res.x;
        #pragma unroll
        for (int t = 0; t < 4; t++) {
            float4 g = reinterpret_cast<const float4*>(boxes)[b * QQ + j0 + t];
            float np = s_npT[labels[b * QQ + j0 + t]][ii];
            bool  vd = area[b * QQ + j0 + t] > 0.0f;
            float hgz = 0.5f * g.z, hgw = 0.5f * g.w;
            float a2 = g.z * g.w;
            float d0 = pc.x - g.x, d1 = pc.y - g.y;
            float d2 = pc.z - hgz, d3 = pc.w - hgw;
            float u = fabsf(d0) + fabsf(d1);
            float v = fabsf(d2) + fabsf(d3);
            float mx = fmaxf(fabsf(d0), fabsf(d2));
            float my = fmaxf(fabsf(d1), fabsf(d3));
            float sz = pc.z + hgz, sw = pc.w + hgw;
            float iwu = sz - mx, ihu = sw - my;
            float ew  = sz + mx, eh  = sw + my;
            float iw = fmaxf(iwu, 0.0f), ih = fmaxf(ihu, 0.0f);
            float inter = iw * ih;
            float enc   = ew * eh;
            float uni   = (a1 + a2) - inter;
            float ru = fast_rcp(uni);
            float re = fast_rcp(enc);
            float base = fmaf(v, 0.5f, np);
            base = fmaf(u, 0.25f, base);
            base = fmaf(-uni, re, base);
            float cost = fmaf(-inter, ru, base);
            r[t] = vd ? cost : BIGV;
        }
        float* op = out + ((size_t)(b * QQ + i0 + ii)) * QQ + j0;
        reinterpret_cast<float4*>(op)[0] = res;
    }
}

extern "C" void kernel_launch(void* const* d_in, const int* in_sizes, int n_in,
                              void* d_out, int out_size) {
    const float* pred_logits = (const float*)d_in[0];  // [B,Q,C]
    const float* pred_boxes  = (const float*)d_in[1];  // [B,Q,4]
    const float* boxes       = (const float*)d_in[2];  // [B,Q,4]
    const float* area        = (const float*)d_in[3];  // [B,Q]
    const int*   labels      = (const int*)d_in[4];    // [B,Q]
    float* out = (float*)d_out;                        // [B,Q,Q]

    dim3 grid(QQ / TI, BB);             // (36, 32) = 1152 blocks
    cost_kernel<<<grid, 256>>>(pred_logits, pred_boxes, boxes, area, labels, out);
}